// round 8
// baseline (speedup 1.0000x reference)
#include <cuda_runtime.h>
#include <cuda_fp16.h>
#include <cstdint>

// AutoInt [8192,64,64] fp32: 3 x { S = X X^T ; A = softmax(S) ; X = A X }.
// One CTA (64 thr, 2 warps) per batch; warp tile m32 x n64. fp16 hi/lo
// 2-term split, 3-pass m16n8k16 HMMA. Softmax + A fragments register-
// resident. ldmatrix.x4 loads; double-buffered X; layer loop not unrolled.
// NO forced launch-bounds min-blocks (3/3 container failures had it).
// This round: register-pressure restructuring so ptxas lands <=~160 regs
// naturally (6 CTAs/SM): single acc array reused across both GEMMs, and
// GEMM1 streams B blocks (A-pair kept, others loaded one at a time).

#define NDIM   64
#define PH     72          // half pitch: 144B rows -> conflict-free ldmatrix
#define LAYERS 3

__device__ __forceinline__ uint32_t h2u(__half2 h) {
    return *reinterpret_cast<uint32_t*>(&h);
}
__device__ __forceinline__ uint32_t sptr(const void* p) {
    return (uint32_t)__cvta_generic_to_shared(p);
}
__device__ __forceinline__ void ldsm4(uint32_t addr, uint32_t r[4]) {
    asm volatile("ldmatrix.sync.aligned.m8n8.x4.shared.b16 {%0,%1,%2,%3}, [%4];"
                 : "=r"(r[0]), "=r"(r[1]), "=r"(r[2]), "=r"(r[3]) : "r"(addr));
}
__device__ __forceinline__ void ldsm4t(uint32_t addr, uint32_t r[4]) {
    asm volatile("ldmatrix.sync.aligned.m8n8.x4.trans.shared.b16 {%0,%1,%2,%3}, [%4];"
                 : "=r"(r[0]), "=r"(r[1]), "=r"(r[2]), "=r"(r[3]) : "r"(addr));
}
__device__ __forceinline__ void mma(float c[4], const uint32_t a[4],
                                    uint32_t b0, uint32_t b1) {
    asm volatile("mma.sync.aligned.m16n8k16.row.col.f32.f16.f16.f32 "
                 "{%0,%1,%2,%3}, {%4,%5,%6,%7}, {%8,%9}, {%0,%1,%2,%3};"
                 : "+f"(c[0]), "+f"(c[1]), "+f"(c[2]), "+f"(c[3])
                 : "r"(a[0]), "r"(a[1]), "r"(a[2]), "r"(a[3]), "r"(b0), "r"(b1));
}
__device__ __forceinline__ void split2(float x, float y, uint32_t& hi, uint32_t& lo) {
    __half2 h = __floats2half2_rn(x, y);
    float2 f = __half22float2(h);
    __half2 l = __floats2half2_rn(x - f.x, y - f.y);
    hi = h2u(h); lo = h2u(l);
}

__global__ __launch_bounds__(64)
void autoint_hmma3_kernel(const float* __restrict__ in, float* __restrict__ out) {
    __shared__ __align__(16) __half Xh[2][NDIM * PH];
    __shared__ __align__(16) __half Xl[2][NDIM * PH];

    const int tid  = threadIdx.x;        // 64 threads, 2 warps
    const int lane = tid & 31;
    const int warp = tid >> 5;           // warp w owns rows 32w..32w+31
    const int gid  = lane >> 2;
    const int tig  = lane & 3;
    const int lrow = lane & 15;          // ldmatrix lane->row
    const int lcol = (lane >> 4) << 3;   // ldmatrix lane->col half (0/8)
    const size_t base = (size_t)blockIdx.x * (NDIM * NDIM);

    // ---- load gmem -> split into Xh/Xl buffer 0 ----
    {
        const float4* src = (const float4*)(in + base);
        #pragma unroll
        for (int i = 0; i < 16; i++) {
            int idx = tid + i * 64;                  // 1024 float4
            float4 v = src[idx];
            int r = idx >> 4, c = (idx & 15) << 2;
            uint32_t h01, l01, h23, l23;
            split2(v.x, v.y, h01, l01);
            split2(v.z, v.w, h23, l23);
            *(uint32_t*)&Xh[0][r * PH + c]     = h01;
            *(uint32_t*)&Xh[0][r * PH + c + 2] = h23;
            *(uint32_t*)&Xl[0][r * PH + c]     = l01;
            *(uint32_t*)&Xl[0][r * PH + c + 2] = l23;
        }
    }
    __syncthreads();

    int cur = 0;
    #pragma unroll 1
    for (int layer = 0; layer < LAYERS; layer++) {
        // Single accumulator array, reused by GEMM1 then GEMM2.
        float acc[2][8][4];
        #pragma unroll
        for (int mh = 0; mh < 2; mh++)
            #pragma unroll
            for (int nt = 0; nt < 8; nt++)
                #pragma unroll
                for (int i = 0; i < 4; i++) acc[mh][nt][i] = 0.0f;

        // ===== GEMM1: S rows 32w..32w+31, all 64 cols (3-pass) =====
        #pragma unroll
        for (int ks = 0; ks < 4; ks++) {
            const int kk = ks * 16;
            // A-pair blocks (rows 32w..32w+31) -- double as B blocks 2w,2w+1
            uint32_t Ah[2][4], Al[2][4];
            #pragma unroll
            for (int p = 0; p < 2; p++) {
                const int b = 2 * warp + p;
                ldsm4(sptr(&Xh[cur][(b * 16 + lrow) * PH + kk + lcol]), Ah[p]);
                ldsm4(sptr(&Xl[cur][(b * 16 + lrow) * PH + kk + lcol]), Al[p]);
            }
            // consume A-pair as B
            #pragma unroll
            for (int p = 0; p < 2; p++) {
                const int b = 2 * warp + p;
                #pragma unroll
                for (int h = 0; h < 2; h++) {
                    const int nt = b * 2 + h;
                    #pragma unroll
                    for (int mh = 0; mh < 2; mh++) {
                        mma(acc[mh][nt], Ah[mh], Ah[p][h], Ah[p][h + 2]);
                        mma(acc[mh][nt], Ah[mh], Al[p][h], Al[p][h + 2]);
                        mma(acc[mh][nt], Al[mh], Ah[p][h], Ah[p][h + 2]);
                    }
                }
            }
            // stream the other warp's two blocks, one at a time
            #pragma unroll
            for (int q = 0; q < 2; q++) {
                const int b = (2 * warp + 2 + q) & 3;
                uint32_t bh[4], bl[4];
                ldsm4(sptr(&Xh[cur][(b * 16 + lrow) * PH + kk + lcol]), bh);
                ldsm4(sptr(&Xl[cur][(b * 16 + lrow) * PH + kk + lcol]), bl);
                #pragma unroll
                for (int h = 0; h < 2; h++) {
                    const int nt = b * 2 + h;
                    #pragma unroll
                    for (int mh = 0; mh < 2; mh++) {
                        mma(acc[mh][nt], Ah[mh], bh[h], bh[h + 2]);
                        mma(acc[mh][nt], Ah[mh], bl[h], bl[h + 2]);
                        mma(acc[mh][nt], Al[mh], bh[h], bh[h + 2]);
                    }
                }
            }
        }

        // ===== softmax (register-resident) + A-frag build =====
        uint32_t AH[2][4][4], AL[2][4][4];
        #pragma unroll
        for (int mh = 0; mh < 2; mh++) {
            float m0 = -1e30f, m1 = -1e30f;
            #pragma unroll
            for (int nt = 0; nt < 8; nt++) {
                m0 = fmaxf(m0, fmaxf(acc[mh][nt][0], acc[mh][nt][1]));
                m1 = fmaxf(m1, fmaxf(acc[mh][nt][2], acc[mh][nt][3]));
            }
            m0 = fmaxf(m0, __shfl_xor_sync(0xffffffffu, m0, 1));
            m0 = fmaxf(m0, __shfl_xor_sync(0xffffffffu, m0, 2));
            m1 = fmaxf(m1, __shfl_xor_sync(0xffffffffu, m1, 1));
            m1 = fmaxf(m1, __shfl_xor_sync(0xffffffffu, m1, 2));
            float s0 = 0.0f, s1 = 0.0f;
            #pragma unroll
            for (int nt = 0; nt < 8; nt++) {
                acc[mh][nt][0] = __expf(acc[mh][nt][0] - m0);
                acc[mh][nt][1] = __expf(acc[mh][nt][1] - m0);
                acc[mh][nt][2] = __expf(acc[mh][nt][2] - m1);
                acc[mh][nt][3] = __expf(acc[mh][nt][3] - m1);
                s0 += acc[mh][nt][0] + acc[mh][nt][1];
                s1 += acc[mh][nt][2] + acc[mh][nt][3];
            }
            s0 += __shfl_xor_sync(0xffffffffu, s0, 1);
            s0 += __shfl_xor_sync(0xffffffffu, s0, 2);
            s1 += __shfl_xor_sync(0xffffffffu, s1, 1);
            s1 += __shfl_xor_sync(0xffffffffu, s1, 2);
            const float inv0 = __fdividef(1.0f, s0);
            const float inv1 = __fdividef(1.0f, s1);
            // C-frag pair (nt=2ks, 2ks+1) == A m16k16 frag for k-chunk ks
            #pragma unroll
            for (int ks = 0; ks < 4; ks++)
                #pragma unroll
                for (int j = 0; j < 2; j++) {
                    int nt = ks * 2 + j;
                    split2(acc[mh][nt][0] * inv0, acc[mh][nt][1] * inv0,
                           AH[mh][ks][2 * j], AL[mh][ks][2 * j]);
                    split2(acc[mh][nt][2] * inv1, acc[mh][nt][3] * inv1,
                           AH[mh][ks][2 * j + 1], AL[mh][ks][2 * j + 1]);
                }
        }

        // re-zero acc; it now serves as GEMM2 accumulator
        #pragma unroll
        for (int mh = 0; mh < 2; mh++)
            #pragma unroll
            for (int nt = 0; nt < 8; nt++)
                #pragma unroll
                for (int i = 0; i < 4; i++) acc[mh][nt][i] = 0.0f;

        // ===== GEMM2: Xnew rows 32w..32w+31 = A X (3-pass) =====
        #pragma unroll
        for (int ks = 0; ks < 4; ks++) {
            const int kk = ks * 16;
            #pragma unroll
            for (int nb4 = 0; nb4 < 4; nb4++) {
                uint32_t th[4], tl[4];
                ldsm4t(sptr(&Xh[cur][(kk + lrow) * PH + nb4 * 16 + lcol]), th);
                ldsm4t(sptr(&Xl[cur][(kk + lrow) * PH + nb4 * 16 + lcol]), tl);
                const int nt = nb4 * 2;
                #pragma unroll
                for (int mh = 0; mh < 2; mh++) {   // B loads amortized over 2 mh
                    mma(acc[mh][nt], AH[mh][ks], th[0], th[1]);
                    mma(acc[mh][nt], AH[mh][ks], tl[0], tl[1]);
                    mma(acc[mh][nt], AL[mh][ks], th[0], th[1]);
                    mma(acc[mh][nt + 1], AH[mh][ks], th[2], th[3]);
                    mma(acc[mh][nt + 1], AH[mh][ks], tl[2], tl[3]);
                    mma(acc[mh][nt + 1], AL[mh][ks], th[2], th[3]);
                }
            }
        }

        if (layer < LAYERS - 1) {
            const int nxt = cur ^ 1;   // other buffer: no WAR hazard
            #pragma unroll
            for (int mh = 0; mh < 2; mh++) {
                const int r0 = warp * 32 + mh * 16 + gid, r1 = r0 + 8;
                #pragma unroll
                for (int nt = 0; nt < 8; nt++) {
                    int col = nt * 8 + 2 * tig;
                    uint32_t h01, l01, h23, l23;
                    split2(acc[mh][nt][0], acc[mh][nt][1], h01, l01);
                    split2(acc[mh][nt][2], acc[mh][nt][3], h23, l23);
                    *(uint32_t*)&Xh[nxt][r0 * PH + col] = h01;
                    *(uint32_t*)&Xl[nxt][r0 * PH + col] = l01;
                    *(uint32_t*)&Xh[nxt][r1 * PH + col] = h23;
                    *(uint32_t*)&Xl[nxt][r1 * PH + col] = l23;
                }
            }
            __syncthreads();
            cur = nxt;
        } else {
            // final layer: fp32 accumulators straight to gmem
            #pragma unroll
            for (int mh = 0; mh < 2; mh++) {
                const int r0 = warp * 32 + mh * 16 + gid, r1 = r0 + 8;
                #pragma unroll
                for (int nt = 0; nt < 8; nt++) {
                    int col = nt * 8 + 2 * tig;
                    *(float2*)&out[base + r0 * NDIM + col] =
                        make_float2(acc[mh][nt][0], acc[mh][nt][1]);
                    *(float2*)&out[base + r1 * NDIM + col] =
                        make_float2(acc[mh][nt][2], acc[mh][nt][3]);
                }
            }
        }
    }
}

extern "C" void kernel_launch(void* const* d_in, const int* in_sizes, int n_in,
                              void* d_out, int out_size) {
    const float* embeds = (const float*)d_in[0];
    float* out = (float*)d_out;
    int batches = in_sizes[0] / (NDIM * NDIM);   // 8192
    autoint_hmma3_kernel<<<batches, 64>>>(embeds, out);
}

// round 9
// speedup vs baseline: 2.4543x; 2.4543x over previous
#include <cuda_runtime.h>
#include <cuda_fp16.h>
#include <cstdint>

// AutoInt [8192,64,64] fp32: 3 x { S = X X^T ; A = softmax(S) ; X = A X }.
// One CTA (64 thr, 2 warps) per batch; warp tile m32 x n64. fp16 hi/lo
// 2-term split, 3-pass m16n8k16 HMMA. R6 structure (best: 247.7us) plus:
// A-lo fragments stashed in the DEAD next-X smem buffer instead of 32
// registers -> true reg demand ~150, 6 CTAs/SM without spills (R8 showed
// restructure-only "reuse" just makes ptxas spill). Per-thread stash at
// byte offset ks*2048 + mh*1024 + tid*16: private (no sync), phase covers
// all 32 banks (conflict-free STS/LDS.128). Epilogue overwrites the stash
// region only after all GEMM2 reads (same-warp program order).
// No launch-bounds min-blocks (3/3 container failures had it); layer loop
// not unrolled (ptxas-safe).

#define NDIM   64
#define PH     72          // half pitch: 144B rows -> conflict-free ldmatrix
#define LAYERS 3

__device__ __forceinline__ uint32_t h2u(__half2 h) {
    return *reinterpret_cast<uint32_t*>(&h);
}
__device__ __forceinline__ uint32_t sptr(const void* p) {
    return (uint32_t)__cvta_generic_to_shared(p);
}
__device__ __forceinline__ void ldsm4(uint32_t addr, uint32_t r[4]) {
    asm volatile("ldmatrix.sync.aligned.m8n8.x4.shared.b16 {%0,%1,%2,%3}, [%4];"
                 : "=r"(r[0]), "=r"(r[1]), "=r"(r[2]), "=r"(r[3]) : "r"(addr));
}
__device__ __forceinline__ void ldsm4t(uint32_t addr, uint32_t r[4]) {
    asm volatile("ldmatrix.sync.aligned.m8n8.x4.trans.shared.b16 {%0,%1,%2,%3}, [%4];"
                 : "=r"(r[0]), "=r"(r[1]), "=r"(r[2]), "=r"(r[3]) : "r"(addr));
}
__device__ __forceinline__ void mma(float c[4], const uint32_t a[4],
                                    uint32_t b0, uint32_t b1) {
    asm volatile("mma.sync.aligned.m16n8k16.row.col.f32.f16.f16.f32 "
                 "{%0,%1,%2,%3}, {%4,%5,%6,%7}, {%8,%9}, {%0,%1,%2,%3};"
                 : "+f"(c[0]), "+f"(c[1]), "+f"(c[2]), "+f"(c[3])
                 : "r"(a[0]), "r"(a[1]), "r"(a[2]), "r"(a[3]), "r"(b0), "r"(b1));
}
__device__ __forceinline__ void split2(float x, float y, uint32_t& hi, uint32_t& lo) {
    __half2 h = __floats2half2_rn(x, y);
    float2 f = __half22float2(h);
    __half2 l = __floats2half2_rn(x - f.x, y - f.y);
    hi = h2u(h); lo = h2u(l);
}

__global__ __launch_bounds__(64)
void autoint_hmma4_kernel(const float* __restrict__ in, float* __restrict__ out) {
    __shared__ __align__(16) __half Xh[2][NDIM * PH];
    __shared__ __align__(16) __half Xl[2][NDIM * PH];

    const int tid  = threadIdx.x;        // 64 threads, 2 warps
    const int lane = tid & 31;
    const int warp = tid >> 5;           // warp w owns rows 32w..32w+31
    const int gid  = lane >> 2;
    const int tig  = lane & 3;
    const int lrow = lane & 15;          // ldmatrix lane->row
    const int lcol = (lane >> 4) << 3;   // ldmatrix lane->col half (0/8)
    const size_t base = (size_t)blockIdx.x * (NDIM * NDIM);

    // ---- load gmem -> split into Xh/Xl buffer 0 ----
    {
        const float4* src = (const float4*)(in + base);
        #pragma unroll
        for (int i = 0; i < 16; i++) {
            int idx = tid + i * 64;                  // 1024 float4
            float4 v = src[idx];
            int r = idx >> 4, c = (idx & 15) << 2;
            uint32_t h01, l01, h23, l23;
            split2(v.x, v.y, h01, l01);
            split2(v.z, v.w, h23, l23);
            *(uint32_t*)&Xh[0][r * PH + c]     = h01;
            *(uint32_t*)&Xh[0][r * PH + c + 2] = h23;
            *(uint32_t*)&Xl[0][r * PH + c]     = l01;
            *(uint32_t*)&Xl[0][r * PH + c + 2] = l23;
        }
    }
    __syncthreads();

    int cur = 0;
    #pragma unroll 1
    for (int layer = 0; layer < LAYERS; layer++) {
        const int nxt = cur ^ 1;
        // AL stash lives in the dead next-X lo buffer (9216B >= 8192B used).
        // Per-thread chunk: bytes [ks*2048 + mh*1024 + tid*16, +16).
        char* stash = (char*)&Xl[nxt][0];

        // ===== GEMM1: S rows 32w..32w+31, all 64 cols (3-pass) =====
        float acc[2][8][4];
        #pragma unroll
        for (int mh = 0; mh < 2; mh++)
            #pragma unroll
            for (int nt = 0; nt < 8; nt++)
                #pragma unroll
                for (int i = 0; i < 4; i++) acc[mh][nt][i] = 0.0f;

        #pragma unroll
        for (int ks = 0; ks < 4; ks++) {
            const int kk = ks * 16;
            uint32_t bh[4][4], bl[4][4];
            #pragma unroll
            for (int nb4 = 0; nb4 < 4; nb4++) {
                ldsm4(sptr(&Xh[cur][(nb4 * 16 + lrow) * PH + kk + lcol]), bh[nb4]);
                ldsm4(sptr(&Xl[cur][(nb4 * 16 + lrow) * PH + kk + lcol]), bl[nb4]);
            }
            // A-frags for m-half mh are bh/bl[2*warp+mh] (same ldmatrix result)
            #pragma unroll
            for (int mh = 0; mh < 2; mh++) {
                const int aw = 2 * warp + mh;
                #pragma unroll
                for (int nb4 = 0; nb4 < 4; nb4++)
                    #pragma unroll
                    for (int h = 0; h < 2; h++) {
                        int nt = nb4 * 2 + h;
                        mma(acc[mh][nt], bh[aw], bh[nb4][h], bh[nb4][h + 2]);
                        mma(acc[mh][nt], bh[aw], bl[nb4][h], bl[nb4][h + 2]);
                        mma(acc[mh][nt], bl[aw], bh[nb4][h], bh[nb4][h + 2]);
                    }
            }
        }

        // ===== softmax (register-resident) + A-frag build =====
        // AH kept in registers; AL written straight to the smem stash.
        uint32_t AH[2][4][4];
        #pragma unroll
        for (int mh = 0; mh < 2; mh++) {
            float m0 = -1e30f, m1 = -1e30f;
            #pragma unroll
            for (int nt = 0; nt < 8; nt++) {
                m0 = fmaxf(m0, fmaxf(acc[mh][nt][0], acc[mh][nt][1]));
                m1 = fmaxf(m1, fmaxf(acc[mh][nt][2], acc[mh][nt][3]));
            }
            m0 = fmaxf(m0, __shfl_xor_sync(0xffffffffu, m0, 1));
            m0 = fmaxf(m0, __shfl_xor_sync(0xffffffffu, m0, 2));
            m1 = fmaxf(m1, __shfl_xor_sync(0xffffffffu, m1, 1));
            m1 = fmaxf(m1, __shfl_xor_sync(0xffffffffu, m1, 2));
            float s0 = 0.0f, s1 = 0.0f;
            #pragma unroll
            for (int nt = 0; nt < 8; nt++) {
                acc[mh][nt][0] = __expf(acc[mh][nt][0] - m0);
                acc[mh][nt][1] = __expf(acc[mh][nt][1] - m0);
                acc[mh][nt][2] = __expf(acc[mh][nt][2] - m1);
                acc[mh][nt][3] = __expf(acc[mh][nt][3] - m1);
                s0 += acc[mh][nt][0] + acc[mh][nt][1];
                s1 += acc[mh][nt][2] + acc[mh][nt][3];
            }
            s0 += __shfl_xor_sync(0xffffffffu, s0, 1);
            s0 += __shfl_xor_sync(0xffffffffu, s0, 2);
            s1 += __shfl_xor_sync(0xffffffffu, s1, 1);
            s1 += __shfl_xor_sync(0xffffffffu, s1, 2);
            const float inv0 = __fdividef(1.0f, s0);
            const float inv1 = __fdividef(1.0f, s1);
            // C-frag pair (nt=2ks, 2ks+1) == A m16k16 frag for k-chunk ks
            #pragma unroll
            for (int ks = 0; ks < 4; ks++) {
                uint32_t alv[4];
                #pragma unroll
                for (int j = 0; j < 2; j++) {
                    int nt = ks * 2 + j;
                    split2(acc[mh][nt][0] * inv0, acc[mh][nt][1] * inv0,
                           AH[mh][ks][2 * j], alv[2 * j]);
                    split2(acc[mh][nt][2] * inv1, acc[mh][nt][3] * inv1,
                           AH[mh][ks][2 * j + 1], alv[2 * j + 1]);
                }
                *(uint4*)(stash + ks * 2048 + mh * 1024 + tid * 16) =
                    make_uint4(alv[0], alv[1], alv[2], alv[3]);
            }
        }

        // ===== GEMM2: Xnew rows 32w..32w+31 = A X (3-pass) =====
        float acc2[2][8][4];
        #pragma unroll
        for (int mh = 0; mh < 2; mh++)
            #pragma unroll
            for (int nt = 0; nt < 8; nt++)
                #pragma unroll
                for (int i = 0; i < 4; i++) acc2[mh][nt][i] = 0.0f;

        #pragma unroll
        for (int ks = 0; ks < 4; ks++) {
            const int kk = ks * 16;
            uint32_t AL2[2][4];
            #pragma unroll
            for (int mh = 0; mh < 2; mh++) {
                uint4 v = *(const uint4*)(stash + ks * 2048 + mh * 1024 + tid * 16);
                AL2[mh][0] = v.x; AL2[mh][1] = v.y;
                AL2[mh][2] = v.z; AL2[mh][3] = v.w;
            }
            #pragma unroll
            for (int nb4 = 0; nb4 < 4; nb4++) {
                uint32_t th[4], tl[4];
                ldsm4t(sptr(&Xh[cur][(kk + lrow) * PH + nb4 * 16 + lcol]), th);
                ldsm4t(sptr(&Xl[cur][(kk + lrow) * PH + nb4 * 16 + lcol]), tl);
                const int nt = nb4 * 2;
                #pragma unroll
                for (int mh = 0; mh < 2; mh++) {   // B loads amortized over 2 mh
                    mma(acc2[mh][nt], AH[mh][ks], th[0], th[1]);
                    mma(acc2[mh][nt], AH[mh][ks], tl[0], tl[1]);
                    mma(acc2[mh][nt], AL2[mh], th[0], th[1]);
                    mma(acc2[mh][nt + 1], AH[mh][ks], th[2], th[3]);
                    mma(acc2[mh][nt + 1], AH[mh][ks], tl[2], tl[3]);
                    mma(acc2[mh][nt + 1], AL2[mh], th[2], th[3]);
                }
            }
        }

        if (layer < LAYERS - 1) {
            // epilogue overwrites the stash region (all AL reads are done)
            #pragma unroll
            for (int mh = 0; mh < 2; mh++) {
                const int r0 = warp * 32 + mh * 16 + gid, r1 = r0 + 8;
                #pragma unroll
                for (int nt = 0; nt < 8; nt++) {
                    int col = nt * 8 + 2 * tig;
                    uint32_t h01, l01, h23, l23;
                    split2(acc2[mh][nt][0], acc2[mh][nt][1], h01, l01);
                    split2(acc2[mh][nt][2], acc2[mh][nt][3], h23, l23);
                    *(uint32_t*)&Xh[nxt][r0 * PH + col] = h01;
                    *(uint32_t*)&Xl[nxt][r0 * PH + col] = l01;
                    *(uint32_t*)&Xh[nxt][r1 * PH + col] = h23;
                    *(uint32_t*)&Xl[nxt][r1 * PH + col] = l23;
                }
            }
            __syncthreads();
            cur = nxt;
        } else {
            // final layer: fp32 accumulators straight to gmem
            #pragma unroll
            for (int mh = 0; mh < 2; mh++) {
                const int r0 = warp * 32 + mh * 16 + gid, r1 = r0 + 8;
                #pragma unroll
                for (int nt = 0; nt < 8; nt++) {
                    int col = nt * 8 + 2 * tig;
                    *(float2*)&out[base + r0 * NDIM + col] =
                        make_float2(acc2[mh][nt][0], acc2[mh][nt][1]);
                    *(float2*)&out[base + r1 * NDIM + col] =
                        make_float2(acc2[mh][nt][2], acc2[mh][nt][3]);
                }
            }
        }
    }
}

extern "C" void kernel_launch(void* const* d_in, const int* in_sizes, int n_in,
                              void* d_out, int out_size) {
    const float* embeds = (const float*)d_in[0];
    float* out = (float*)d_out;
    int batches = in_sizes[0] / (NDIM * NDIM);   // 8192
    autoint_hmma4_kernel<<<batches, 64>>>(embeds, out);
}